// round 3
// baseline (speedup 1.0000x reference)
#include <cuda_runtime.h>

// ---------------------------------------------------------------------------
// 2-layer LSTM (H=51), T=2048 + 16 future steps, B=512.
// R3: cross-layer software pipelining. Tick tau runs concurrently:
//   L1 warps   : layer-1 step tau      (gate dot + activation)
//   L2 warps   : layer-2 step tau-1    (k-split halves, gate dot + activation)
//   out spares : output dot for step tau-2
//   x  spares  : prefetch x[tau+1]
// 2 barriers per tick (vs 5). Weights in registers. f32x2 packed FMA.
// Future steps (autoregressive) run in a short serial epilogue.
// ---------------------------------------------------------------------------

#define H    51
#define G4   204
#define T    2048
#define FUT  16
#define TT   (T + FUT)
#define NB   4
#define NBLK 128
#define WP   52
#define GP   208
#define NTH  640          // 20 warps

typedef unsigned long long u64;

__device__ __forceinline__ u64 pack2(float lo, float hi) {
    u64 r; asm("mov.b64 %0, {%1,%2};" : "=l"(r) : "f"(lo), "f"(hi)); return r;
}
__device__ __forceinline__ u64 ffma2(u64 a, u64 b, u64 c) {
    u64 d; asm("fma.rn.f32x2 %0, %1, %2, %3;" : "=l"(d) : "l"(a), "l"(b), "l"(c));
    return d;
}
__device__ __forceinline__ float hsum2(u64 a) {
    float lo, hi; asm("mov.b64 {%0,%1}, %2;" : "=f"(lo), "=f"(hi) : "l"(a));
    return lo + hi;
}
__device__ __forceinline__ float sigf(float x) {
    return __fdividef(1.f, 1.f + __expf(-x));
}
__device__ __forceinline__ float tanh_fast(float x) {
    float xc = fminf(fmaxf(x, -15.f), 15.f);
    float e  = __expf(2.f * xc);
    return __fdividef(e - 1.f, e + 1.f);
}
__device__ __forceinline__ float lstm_act(float gi, float gf, float gg, float go, float& c) {
    c = sigf(gf) * c + sigf(gi) * tanh_fast(gg);
    return sigf(go) * tanh_fast(c);
}

struct __align__(16) Smem {
    float h1[2][NB][WP];     // double-buffered hidden states (pad col 51 = 0)
    float h2[2][NB][WP];
    float G1[NB][GP];        // layer-1 gate values
    float G2[2][NB][GP];     // layer-2 gate partial sums (two k-halves)
    float WL[WP];            // W_lin padded
    float X[2][NB];          // double-buffered input scalar
    float OUTB[NB];          // last output (autoregressive feed)
    float blin;
};

__global__ __launch_bounds__(NTH, 1)
void lstm_pipe_kernel(const float* __restrict__ input,
                      const float* __restrict__ Wih1,
                      const float* __restrict__ Whh1,
                      const float* __restrict__ bih1,
                      const float* __restrict__ bhh1,
                      const float* __restrict__ Wih2,
                      const float* __restrict__ Whh2,
                      const float* __restrict__ bih2,
                      const float* __restrict__ bhh2,
                      const float* __restrict__ Wlin,
                      const float* __restrict__ blin,
                      float* __restrict__ out)
{
    __shared__ Smem s;
    const int j   = threadIdx.x;
    const int bb0 = blockIdx.x * NB;

    const bool isL1 = (j < G4);
    const bool isH0 = (j >= 204 && j < 408);   // L2 k-half 0: k 0..27
    const bool isH1 = (j >= 408 && j < 612);   // L2 k-half 1: k 28..51
    const bool isOut = (j >= 612 && j < 616);
    const bool isX   = (j >= 616 && j < 620);
    const int m0 = j - 204;                    // half0 row
    const int m1 = j - 408;                    // half1 row

    // ---------------- prologue: weights to registers ----------------
    u64 w1[26];                 // L1: Whh1 row (26 f32x2 pairs)
    u64 wa[14], wb[14];         // L2: Wih2 / Whh2 half-rows
    float bj1 = 0.f, wi1 = 0.f, bj2 = 0.f;

    if (isL1) {
        const float* r1 = Whh1 + j * H;
        #pragma unroll
        for (int p = 0; p < 26; p++) {
            int k1 = 2 * p + 1;
            w1[p] = pack2(r1[2 * p], (k1 < H) ? r1[k1] : 0.f);
        }
        bj1 = bih1[j] + bhh1[j];
        wi1 = Wih1[j];
    }
    if (isH0) {
        const float* ra = Wih2 + m0 * H;
        const float* rb = Whh2 + m0 * H;
        #pragma unroll
        for (int p = 0; p < 14; p++) {          // k 0..27, all valid
            wa[p] = pack2(ra[2 * p], ra[2 * p + 1]);
            wb[p] = pack2(rb[2 * p], rb[2 * p + 1]);
        }
        bj2 = bih2[m0] + bhh2[m0];
    }
    if (isH1) {
        const float* ra = Wih2 + m1 * H;
        const float* rb = Whh2 + m1 * H;
        #pragma unroll
        for (int p = 0; p < 12; p++) {          // k 28..51 (k=51 -> 0 pad)
            int k0 = 28 + 2 * p, k1 = k0 + 1;
            wa[p] = pack2(ra[k0], (k1 < H) ? ra[k1] : 0.f);
            wb[p] = pack2(rb[k0], (k1 < H) ? rb[k1] : 0.f);
        }
    }

    // zero state buffers
    for (int idx = j; idx < 2 * NB * WP; idx += NTH) {
        (&s.h1[0][0][0])[idx] = 0.f;
        (&s.h2[0][0][0])[idx] = 0.f;
    }
    if (j < WP)  s.WL[j] = (j < H) ? Wlin[j] : 0.f;
    if (j < NB) {
        s.X[0][j]  = input[(size_t)(bb0 + j) * T];
        s.X[1][j]  = 0.f;
        s.OUTB[j]  = 0.f;
    }
    if (j == 0) s.blin = blin[0];

    // update-phase ownership
    const int ub = isL1 ? (j / H)  : 0;   // L1 update: (batch, unit)
    const int uu = isL1 ? (j % H)  : 0;
    const int b2 = isH0 ? (m0 / H) : 0;   // L2 update (half0 threads own c2)
    const int u2 = isH0 ? (m0 % H) : 0;

    float c1 = 0.f, c2 = 0.f;
    __syncthreads();

    // --------------------------- pipelined main loop ---------------------------
    for (int tau = 0; tau <= T + 1; tau++) {
        const int pA = tau & 1, pB = pA ^ 1;
        const bool l1act  = (tau < T);
        const bool l2act  = (tau >= 1 && tau <= T);
        const bool outact = (tau >= 2);
        float xr = 0.f;

        // ================= dot phase =================
        if (isX && tau <= T - 2)
            xr = input[(size_t)(bb0 + (j - 616)) * T + (tau + 1)];

        if (isL1 && l1act) {                 // layer-1 gates, step tau
            u64 acc[NB];
            #pragma unroll
            for (int b = 0; b < NB; b++)
                acc[b] = pack2(fmaf(wi1, s.X[pA][b], bj1), 0.f);
            #pragma unroll
            for (int p = 0; p < 13; p++) {
                #pragma unroll
                for (int b = 0; b < NB; b++) {
                    ulonglong2 hv = *(const ulonglong2*)&s.h1[pB][b][4 * p];
                    acc[b] = ffma2(w1[2 * p],     hv.x, acc[b]);
                    acc[b] = ffma2(w1[2 * p + 1], hv.y, acc[b]);
                }
            }
            #pragma unroll
            for (int b = 0; b < NB; b++) s.G1[b][j] = hsum2(acc[b]);
        }

        if (isH0 && l2act) {                 // layer-2 gates (k 0..27), step tau-1
            u64 acc[NB];
            #pragma unroll
            for (int b = 0; b < NB; b++) acc[b] = pack2(bj2, 0.f);
            #pragma unroll
            for (int p = 0; p < 7; p++) {
                #pragma unroll
                for (int b = 0; b < NB; b++) {
                    ulonglong2 h1v = *(const ulonglong2*)&s.h1[pB][b][4 * p];
                    ulonglong2 h2v = *(const ulonglong2*)&s.h2[pA][b][4 * p];
                    acc[b] = ffma2(wa[2 * p],     h1v.x, acc[b]);
                    acc[b] = ffma2(wa[2 * p + 1], h1v.y, acc[b]);
                    acc[b] = ffma2(wb[2 * p],     h2v.x, acc[b]);
                    acc[b] = ffma2(wb[2 * p + 1], h2v.y, acc[b]);
                }
            }
            #pragma unroll
            for (int b = 0; b < NB; b++) s.G2[0][b][m0] = hsum2(acc[b]);
        }

        if (isH1 && l2act) {                 // layer-2 gates (k 28..51)
            u64 acc[NB];
            #pragma unroll
            for (int b = 0; b < NB; b++) acc[b] = pack2(0.f, 0.f);
            #pragma unroll
            for (int p = 0; p < 6; p++) {
                #pragma unroll
                for (int b = 0; b < NB; b++) {
                    ulonglong2 h1v = *(const ulonglong2*)&s.h1[pB][b][28 + 4 * p];
                    ulonglong2 h2v = *(const ulonglong2*)&s.h2[pA][b][28 + 4 * p];
                    acc[b] = ffma2(wa[2 * p],     h1v.x, acc[b]);
                    acc[b] = ffma2(wa[2 * p + 1], h1v.y, acc[b]);
                    acc[b] = ffma2(wb[2 * p],     h2v.x, acc[b]);
                    acc[b] = ffma2(wb[2 * p + 1], h2v.y, acc[b]);
                }
            }
            #pragma unroll
            for (int b = 0; b < NB; b++) s.G2[1][b][m1] = hsum2(acc[b]);
        }

        if (isOut && outact) {               // output dot, step tau-2
            const int b = j - 612;
            const int sstep = tau - 2;
            float a0 = 0.f, a1 = 0.f, a2 = 0.f, a3 = 0.f;
            #pragma unroll
            for (int p = 0; p < 13; p++) {
                float4 w = *(const float4*)&s.WL[4 * p];
                float4 h = *(const float4*)&s.h2[pA][b][4 * p];
                a0 = fmaf(w.x, h.x, a0);  a1 = fmaf(w.y, h.y, a1);
                a2 = fmaf(w.z, h.z, a2);  a3 = fmaf(w.w, h.w, a3);
            }
            float val = (a0 + a1) + (a2 + a3) + s.blin;
            out[(size_t)(bb0 + b) * TT + sstep] = val;
            s.OUTB[b] = val;
        }
        __syncthreads();    // gates (G1, G2) visible

        // ================= update phase =================
        if (isL1 && l1act) {
            float gi = s.G1[ub][uu],       gf = s.G1[ub][H + uu];
            float gg = s.G1[ub][2*H + uu], go = s.G1[ub][3*H + uu];
            s.h1[pA][ub][uu] = lstm_act(gi, gf, gg, go, c1);
        }
        if (isH0 && l2act) {
            float gi = s.G2[0][b2][u2]       + s.G2[1][b2][u2];
            float gf = s.G2[0][b2][H + u2]   + s.G2[1][b2][H + u2];
            float gg = s.G2[0][b2][2*H + u2] + s.G2[1][b2][2*H + u2];
            float go = s.G2[0][b2][3*H + u2] + s.G2[1][b2][3*H + u2];
            s.h2[pB][b2][u2] = lstm_act(gi, gf, gg, go, c2);
        }
        if (isX && tau <= T - 2) s.X[pB][j - 616] = xr;
        __syncthreads();    // h1[pA], h2[pB], X[pB] visible
    }

    // --------------------- serial autoregressive epilogue ---------------------
    for (int sstep = T; sstep < TT; sstep++) {
        const int pA = sstep & 1, pB = pA ^ 1;

        if (isL1) {                              // gate1, x = previous output
            u64 acc[NB];
            #pragma unroll
            for (int b = 0; b < NB; b++)
                acc[b] = pack2(fmaf(wi1, s.OUTB[b], bj1), 0.f);
            #pragma unroll
            for (int p = 0; p < 13; p++) {
                #pragma unroll
                for (int b = 0; b < NB; b++) {
                    ulonglong2 hv = *(const ulonglong2*)&s.h1[pB][b][4 * p];
                    acc[b] = ffma2(w1[2 * p],     hv.x, acc[b]);
                    acc[b] = ffma2(w1[2 * p + 1], hv.y, acc[b]);
                }
            }
            #pragma unroll
            for (int b = 0; b < NB; b++) s.G1[b][j] = hsum2(acc[b]);
        }
        __syncthreads();
        if (isL1) {
            float gi = s.G1[ub][uu],       gf = s.G1[ub][H + uu];
            float gg = s.G1[ub][2*H + uu], go = s.G1[ub][3*H + uu];
            s.h1[pA][ub][uu] = lstm_act(gi, gf, gg, go, c1);
        }
        __syncthreads();
        if (isH0) {
            u64 acc[NB];
            #pragma unroll
            for (int b = 0; b < NB; b++) acc[b] = pack2(bj2, 0.f);
            #pragma unroll
            for (int p = 0; p < 7; p++) {
                #pragma unroll
                for (int b = 0; b < NB; b++) {
                    ulonglong2 h1v = *(const ulonglong2*)&s.h1[pA][b][4 * p];
                    ulonglong2 h2v = *(const ulonglong2*)&s.h2[pB][b][4 * p];
                    acc[b] = ffma2(wa[2 * p],     h1v.x, acc[b]);
                    acc[b] = ffma2(wa[2 * p + 1], h1v.y, acc[b]);
                    acc[b] = ffma2(wb[2 * p],     h2v.x, acc[b]);
                    acc[b] = ffma2(wb[2 * p + 1], h2v.y, acc[b]);
                }
            }
            #pragma unroll
            for (int b = 0; b < NB; b++) s.G2[0][b][m0] = hsum2(acc[b]);
        }
        if (isH1) {
            u64 acc[NB];
            #pragma unroll
            for (int b = 0; b < NB; b++) acc[b] = pack2(0.f, 0.f);
            #pragma unroll
            for (int p = 0; p < 6; p++) {
                #pragma unroll
                for (int b = 0; b < NB; b++) {
                    ulonglong2 h1v = *(const ulonglong2*)&s.h1[pA][b][28 + 4 * p];
                    ulonglong2 h2v = *(const ulonglong2*)&s.h2[pB][b][28 + 4 * p];
                    acc[b] = ffma2(wa[2 * p],     h1v.x, acc[b]);
                    acc[b] = ffma2(wa[2 * p + 1], h1v.y, acc[b]);
                    acc[b] = ffma2(wb[2 * p],     h2v.x, acc[b]);
                    acc[b] = ffma2(wb[2 * p + 1], h2v.y, acc[b]);
                }
            }
            #pragma unroll
            for (int b = 0; b < NB; b++) s.G2[1][b][m1] = hsum2(acc[b]);
        }
        __syncthreads();
        if (isH0) {
            float gi = s.G2[0][b2][u2]       + s.G2[1][b2][u2];
            float gf = s.G2[0][b2][H + u2]   + s.G2[1][b2][H + u2];
            float gg = s.G2[0][b2][2*H + u2] + s.G2[1][b2][2*H + u2];
            float go = s.G2[0][b2][3*H + u2] + s.G2[1][b2][3*H + u2];
            s.h2[pA][b2][u2] = lstm_act(gi, gf, gg, go, c2);
        }
        __syncthreads();
        if (isOut) {
            const int b = j - 612;
            float a0 = 0.f, a1 = 0.f, a2 = 0.f, a3 = 0.f;
            #pragma unroll
            for (int p = 0; p < 13; p++) {
                float4 w = *(const float4*)&s.WL[4 * p];
                float4 h = *(const float4*)&s.h2[pA][b][4 * p];
                a0 = fmaf(w.x, h.x, a0);  a1 = fmaf(w.y, h.y, a1);
                a2 = fmaf(w.z, h.z, a2);  a3 = fmaf(w.w, h.w, a3);
            }
            float val = (a0 + a1) + (a2 + a3) + s.blin;
            out[(size_t)(bb0 + b) * TT + sstep] = val;
            s.OUTB[b] = val;
        }
        __syncthreads();
    }
}

extern "C" void kernel_launch(void* const* d_in, const int* in_sizes, int n_in,
                              void* d_out, int out_size)
{
    const float* input = (const float*)d_in[0];
    const float* Wih1  = (const float*)d_in[1];
    const float* Whh1  = (const float*)d_in[2];
    const float* bih1  = (const float*)d_in[3];
    const float* bhh1  = (const float*)d_in[4];
    const float* Wih2  = (const float*)d_in[5];
    const float* Whh2  = (const float*)d_in[6];
    const float* bih2  = (const float*)d_in[7];
    const float* bhh2  = (const float*)d_in[8];
    const float* Wlin  = (const float*)d_in[9];
    const float* blin  = (const float*)d_in[10];
    float* out = (float*)d_out;

    lstm_pipe_kernel<<<NBLK, NTH>>>(
        input, Wih1, Whh1, bih1, bhh1, Wih2, Whh2, bih2, bhh2, Wlin, blin, out);
}

// round 4
// speedup vs baseline: 1.6634x; 1.6634x over previous
#include <cuda_runtime.h>

// ---------------------------------------------------------------------------
// 2-layer LSTM (H=51), T=2048 + 16 future steps, B=512.
// R4: cross-layer pipeline with spill-proof registers.
//   warps 0-6  (thr 0..203)  : layer-1 step tau   (Whh1 row in wreg[0..25])
//   warp 6 tail(thr 204..211): output dot (tau-2) + x prefetch (tau+1)
//   warps 7-13 (thr 224..427): layer-2 step tau-1 (Wih2/Whh2 rows in wreg[0..51])
// One union weight array per thread -> no register-allocation blowup.
// 2 barriers per tick. Serial epilogue for the 16 autoregressive steps.
// ---------------------------------------------------------------------------

#define H    51
#define G4   204
#define T    2048
#define FUT  16
#define TT   (T + FUT)
#define NB   4
#define NBLK 128
#define WP   52
#define GP   208
#define NTH  448          // 14 warps

typedef unsigned long long u64;

__device__ __forceinline__ u64 pack2(float lo, float hi) {
    u64 r; asm("mov.b64 %0, {%1,%2};" : "=l"(r) : "f"(lo), "f"(hi)); return r;
}
__device__ __forceinline__ u64 ffma2(u64 a, u64 b, u64 c) {
    u64 d; asm("fma.rn.f32x2 %0, %1, %2, %3;" : "=l"(d) : "l"(a), "l"(b), "l"(c));
    return d;
}
__device__ __forceinline__ float hsum2(u64 a) {
    float lo, hi; asm("mov.b64 {%0,%1}, %2;" : "=f"(lo), "=f"(hi) : "l"(a));
    return lo + hi;
}
__device__ __forceinline__ float sigf(float x) {
    return __fdividef(1.f, 1.f + __expf(-x));
}
__device__ __forceinline__ float tanh_fast(float x) {
    float xc = fminf(fmaxf(x, -15.f), 15.f);
    float e  = __expf(2.f * xc);
    return __fdividef(e - 1.f, e + 1.f);
}
__device__ __forceinline__ float lstm_act(float gi, float gf, float gg, float go, float& c) {
    c = sigf(gf) * c + sigf(gi) * tanh_fast(gg);
    return sigf(go) * tanh_fast(c);
}

struct __align__(16) Smem {
    float h1[2][NB][WP];     // double-buffered hidden states (pad col 51 = 0)
    float h2[2][NB][WP];
    float G1[NB][GP];        // layer-1 gate values
    float G2[NB][GP];        // layer-2 gate values
    float WL[WP];            // W_lin padded
    float X[2][NB];          // double-buffered input scalar
    float OUTB[NB];          // last output (autoregressive feed)
    float blin;
};

__global__ __launch_bounds__(NTH, 1)
void lstm_pipe_kernel(const float* __restrict__ input,
                      const float* __restrict__ Wih1,
                      const float* __restrict__ Whh1,
                      const float* __restrict__ bih1,
                      const float* __restrict__ bhh1,
                      const float* __restrict__ Wih2,
                      const float* __restrict__ Whh2,
                      const float* __restrict__ bih2,
                      const float* __restrict__ bhh2,
                      const float* __restrict__ Wlin,
                      const float* __restrict__ blin,
                      float* __restrict__ out)
{
    __shared__ Smem s;
    const int j   = threadIdx.x;
    const int bb0 = blockIdx.x * NB;

    const bool isL1  = (j < G4);
    const bool isOut = (j >= 204 && j < 208);
    const bool isX   = (j >= 208 && j < 212);
    const bool isL2  = (j >= 224 && j < 224 + G4);
    const int  m     = j - 224;                 // L2 row

    // ---------------- prologue: weights to registers (union array) ----------
    u64 wreg[52];                // L1: [0..25]=Whh1 row.  L2: [0..25]=Wih2, [26..51]=Whh2.
    float bj = 0.f, wi1 = 0.f;

    if (isL1) {
        const float* r1 = Whh1 + j * H;
        #pragma unroll
        for (int p = 0; p < 26; p++) {
            int k1 = 2 * p + 1;
            wreg[p] = pack2(r1[2 * p], (k1 < H) ? r1[k1] : 0.f);
        }
        bj  = bih1[j] + bhh1[j];
        wi1 = Wih1[j];
    }
    if (isL2) {
        const float* ra = Wih2 + m * H;
        const float* rb = Whh2 + m * H;
        #pragma unroll
        for (int p = 0; p < 26; p++) {
            int k1 = 2 * p + 1;
            wreg[p]      = pack2(ra[2 * p], (k1 < H) ? ra[k1] : 0.f);
            wreg[26 + p] = pack2(rb[2 * p], (k1 < H) ? rb[k1] : 0.f);
        }
        bj = bih2[m] + bhh2[m];
    }

    // zero state buffers
    for (int idx = j; idx < 2 * NB * WP; idx += NTH) {
        (&s.h1[0][0][0])[idx] = 0.f;
        (&s.h2[0][0][0])[idx] = 0.f;
    }
    if (j < WP)  s.WL[j] = (j < H) ? Wlin[j] : 0.f;
    if (j < NB) {
        s.X[0][j]  = input[(size_t)(bb0 + j) * T];
        s.X[1][j]  = 0.f;
        s.OUTB[j]  = 0.f;
    }
    if (j == 0) s.blin = blin[0];

    // update-phase ownership
    const int ub = isL1 ? (j / H) : 0;    // L1 update (batch, unit)
    const int uu = isL1 ? (j % H) : 0;
    const int b2 = isL2 ? (m / H) : 0;    // L2 update (batch, unit)
    const int u2 = isL2 ? (m % H) : 0;

    float c1 = 0.f, c2 = 0.f;
    __syncthreads();

    // --------------------------- pipelined main loop ---------------------------
    for (int tau = 0; tau <= T + 1; tau++) {
        const int pA = tau & 1, pB = pA ^ 1;
        const bool l1act  = (tau < T);
        const bool l2act  = (tau >= 1 && tau <= T);
        const bool outact = (tau >= 2);
        float xr = 0.f;

        // ================= dot phase =================
        if (isX && tau <= T - 2)
            xr = input[(size_t)(bb0 + (j - 208)) * T + (tau + 1)];

        if (isL1 && l1act) {                 // layer-1 gates, step tau
            u64 acc[NB];
            #pragma unroll
            for (int b = 0; b < NB; b++)
                acc[b] = pack2(fmaf(wi1, s.X[pA][b], bj), 0.f);
            #pragma unroll
            for (int p = 0; p < 13; p++) {
                #pragma unroll
                for (int b = 0; b < NB; b++) {
                    ulonglong2 hv = *(const ulonglong2*)&s.h1[pB][b][4 * p];
                    acc[b] = ffma2(wreg[2 * p],     hv.x, acc[b]);
                    acc[b] = ffma2(wreg[2 * p + 1], hv.y, acc[b]);
                }
            }
            #pragma unroll
            for (int b = 0; b < NB; b++) s.G1[b][j] = hsum2(acc[b]);
        }

        if (isL2 && l2act) {                 // layer-2 gates, step tau-1
            u64 acc[NB];
            #pragma unroll
            for (int b = 0; b < NB; b++) acc[b] = pack2(bj, 0.f);
            #pragma unroll
            for (int p = 0; p < 13; p++) {
                #pragma unroll
                for (int b = 0; b < NB; b++) {
                    ulonglong2 h1v = *(const ulonglong2*)&s.h1[pB][b][4 * p];
                    ulonglong2 h2v = *(const ulonglong2*)&s.h2[pA][b][4 * p];
                    acc[b] = ffma2(wreg[2 * p],          h1v.x, acc[b]);
                    acc[b] = ffma2(wreg[2 * p + 1],      h1v.y, acc[b]);
                    acc[b] = ffma2(wreg[26 + 2 * p],     h2v.x, acc[b]);
                    acc[b] = ffma2(wreg[26 + 2 * p + 1], h2v.y, acc[b]);
                }
            }
            #pragma unroll
            for (int b = 0; b < NB; b++) s.G2[b][m] = hsum2(acc[b]);
        }

        if (isOut && outact) {               // output dot, step tau-2
            const int b = j - 204;
            float a0 = 0.f, a1 = 0.f, a2 = 0.f, a3 = 0.f;
            #pragma unroll
            for (int p = 0; p < 13; p++) {
                float4 w = *(const float4*)&s.WL[4 * p];
                float4 h = *(const float4*)&s.h2[pA][b][4 * p];
                a0 = fmaf(w.x, h.x, a0);  a1 = fmaf(w.y, h.y, a1);
                a2 = fmaf(w.z, h.z, a2);  a3 = fmaf(w.w, h.w, a3);
            }
            float val = (a0 + a1) + (a2 + a3) + s.blin;
            out[(size_t)(bb0 + b) * TT + (tau - 2)] = val;
            s.OUTB[b] = val;
        }
        __syncthreads();    // G1, G2 visible

        // ================= update phase =================
        if (isL1 && l1act) {
            float gi = s.G1[ub][uu],       gf = s.G1[ub][H + uu];
            float gg = s.G1[ub][2*H + uu], go = s.G1[ub][3*H + uu];
            s.h1[pA][ub][uu] = lstm_act(gi, gf, gg, go, c1);
        }
        if (isL2 && l2act) {
            float gi = s.G2[b2][u2],       gf = s.G2[b2][H + u2];
            float gg = s.G2[b2][2*H + u2], go = s.G2[b2][3*H + u2];
            s.h2[pB][b2][u2] = lstm_act(gi, gf, gg, go, c2);
        }
        if (isX && tau <= T - 2) s.X[pB][j - 208] = xr;
        __syncthreads();    // h1[pA], h2[pB], X[pB] visible
    }

    // --------------------- serial autoregressive epilogue ---------------------
    for (int sstep = T; sstep < TT; sstep++) {
        const int pA = sstep & 1, pB = pA ^ 1;

        if (isL1) {                              // gate1, x = previous output
            u64 acc[NB];
            #pragma unroll
            for (int b = 0; b < NB; b++)
                acc[b] = pack2(fmaf(wi1, s.OUTB[b], bj), 0.f);
            #pragma unroll
            for (int p = 0; p < 13; p++) {
                #pragma unroll
                for (int b = 0; b < NB; b++) {
                    ulonglong2 hv = *(const ulonglong2*)&s.h1[pB][b][4 * p];
                    acc[b] = ffma2(wreg[2 * p],     hv.x, acc[b]);
                    acc[b] = ffma2(wreg[2 * p + 1], hv.y, acc[b]);
                }
            }
            #pragma unroll
            for (int b = 0; b < NB; b++) s.G1[b][j] = hsum2(acc[b]);
        }
        __syncthreads();
        if (isL1) {
            float gi = s.G1[ub][uu],       gf = s.G1[ub][H + uu];
            float gg = s.G1[ub][2*H + uu], go = s.G1[ub][3*H + uu];
            s.h1[pA][ub][uu] = lstm_act(gi, gf, gg, go, c1);
        }
        __syncthreads();
        if (isL2) {
            u64 acc[NB];
            #pragma unroll
            for (int b = 0; b < NB; b++) acc[b] = pack2(bj, 0.f);
            #pragma unroll
            for (int p = 0; p < 13; p++) {
                #pragma unroll
                for (int b = 0; b < NB; b++) {
                    ulonglong2 h1v = *(const ulonglong2*)&s.h1[pA][b][4 * p];
                    ulonglong2 h2v = *(const ulonglong2*)&s.h2[pB][b][4 * p];
                    acc[b] = ffma2(wreg[2 * p],          h1v.x, acc[b]);
                    acc[b] = ffma2(wreg[2 * p + 1],      h1v.y, acc[b]);
                    acc[b] = ffma2(wreg[26 + 2 * p],     h2v.x, acc[b]);
                    acc[b] = ffma2(wreg[26 + 2 * p + 1], h2v.y, acc[b]);
                }
            }
            #pragma unroll
            for (int b = 0; b < NB; b++) s.G2[b][m] = hsum2(acc[b]);
        }
        __syncthreads();
        if (isL2) {
            float gi = s.G2[b2][u2],       gf = s.G2[b2][H + u2];
            float gg = s.G2[b2][2*H + u2], go = s.G2[b2][3*H + u2];
            s.h2[pA][b2][u2] = lstm_act(gi, gf, gg, go, c2);
        }
        __syncthreads();
        if (isOut) {
            const int b = j - 204;
            float a0 = 0.f, a1 = 0.f, a2 = 0.f, a3 = 0.f;
            #pragma unroll
            for (int p = 0; p < 13; p++) {
                float4 w = *(const float4*)&s.WL[4 * p];
                float4 h = *(const float4*)&s.h2[pA][b][4 * p];
                a0 = fmaf(w.x, h.x, a0);  a1 = fmaf(w.y, h.y, a1);
                a2 = fmaf(w.z, h.z, a2);  a3 = fmaf(w.w, h.w, a3);
            }
            float val = (a0 + a1) + (a2 + a3) + s.blin;
            out[(size_t)(bb0 + b) * TT + sstep] = val;
            s.OUTB[b] = val;
        }
        __syncthreads();
    }
}

extern "C" void kernel_launch(void* const* d_in, const int* in_sizes, int n_in,
                              void* d_out, int out_size)
{
    const float* input = (const float*)d_in[0];
    const float* Wih1  = (const float*)d_in[1];
    const float* Whh1  = (const float*)d_in[2];
    const float* bih1  = (const float*)d_in[3];
    const float* bhh1  = (const float*)d_in[4];
    const float* Wih2  = (const float*)d_in[5];
    const float* Whh2  = (const float*)d_in[6];
    const float* bih2  = (const float*)d_in[7];
    const float* bhh2  = (const float*)d_in[8];
    const float* Wlin  = (const float*)d_in[9];
    const float* blin  = (const float*)d_in[10];
    float* out = (float*)d_out;

    lstm_pipe_kernel<<<NBLK, NTH>>>(
        input, Wih1, Whh1, bih1, bhh1, Wih2, Whh2, bih2, bhh2, Wlin, blin, out);
}

// round 6
// speedup vs baseline: 1.9956x; 1.1997x over previous
#include <cuda_runtime.h>

// ---------------------------------------------------------------------------
// 2-layer LSTM (H=51), T=2048 + 16 autoregressive steps, B=512.
// R6 (= R5 resubmit; R5 hit a broker infra failure, never executed):
// serial 5-phase structure (like R2) but each gate row is split across
// TWO threads by k-half -> 13 balanced worker warps for latency hiding.
//   warps 0-6  (thr 0..203)   : half0 (k 0..27)  + own c1 (update1)
//   warp 6 tail(thr 204..211) : out-dot (step t-1) / x prefetch
//   warps 7-13 (thr 224..427) : half1 (k 28..51) + own c2 (update2)
// Partials interleave at gate-buffer column 2r+h -> update reads LDS.64 pair.
// 4 barriers per main step; out-dot runs concurrently with gate1.
// ---------------------------------------------------------------------------

#define H     51
#define G4    204
#define T     2048
#define FUT   16
#define TT    (T + FUT)
#define NB    4
#define NBLK  128
#define WPAD  56          // padded h row (floats; 51..55 = 0)
#define GPIT  424         // gate buffer pitch (cols 0..407 used)
#define NTH   448         // 14 warps

typedef unsigned long long u64;

__device__ __forceinline__ u64 pack2(float lo, float hi) {
    u64 r; asm("mov.b64 %0, {%1,%2};" : "=l"(r) : "f"(lo), "f"(hi)); return r;
}
__device__ __forceinline__ u64 ffma2(u64 a, u64 b, u64 c) {
    u64 d; asm("fma.rn.f32x2 %0, %1, %2, %3;" : "=l"(d) : "l"(a), "l"(b), "l"(c));
    return d;
}
__device__ __forceinline__ float hsum2(u64 a) {
    float lo, hi; asm("mov.b64 {%0,%1}, %2;" : "=f"(lo), "=f"(hi) : "l"(a));
    return lo + hi;
}
__device__ __forceinline__ float sigf(float x) {
    return __fdividef(1.f, 1.f + __expf(-x));
}
__device__ __forceinline__ float tanh_fast(float x) {
    float xc = fminf(fmaxf(x, -15.f), 15.f);
    float e  = __expf(2.f * xc);
    return __fdividef(e - 1.f, e + 1.f);
}
__device__ __forceinline__ float lstm_act(float gi, float gf, float gg, float go, float& c) {
    c = sigf(gf) * c + sigf(gi) * tanh_fast(gg);
    return sigf(go) * tanh_fast(c);
}

struct __align__(16) Smem {
    float h1[NB][WPAD];
    float h2[NB][WPAD];
    float G1[NB][GPIT];     // interleaved partials: col 2r+h
    float G2[NB][GPIT];
    float WL[WPAD];         // W_lin padded
    float X[NB];
    float OUTB[NB];
    float blin;
};

// load one k-half (7 float4 chunks starting at float offset ko) as 14 f32x2 pairs
__device__ __forceinline__ void load_half(const float* row, int ko, u64* w) {
    #pragma unroll
    for (int c = 0; c < 7; c++) {
        #pragma unroll
        for (int q = 0; q < 2; q++) {
            int k0 = ko + 4 * c + 2 * q, k1 = k0 + 1;
            float a = (k0 < H) ? row[k0] : 0.f;
            float b = (k1 < H) ? row[k1] : 0.f;
            w[2 * c + q] = pack2(a, b);
        }
    }
}

__global__ __launch_bounds__(NTH, 1)
void lstm_ksplit_kernel(const float* __restrict__ input,
                        const float* __restrict__ Wih1,
                        const float* __restrict__ Whh1,
                        const float* __restrict__ bih1,
                        const float* __restrict__ bhh1,
                        const float* __restrict__ Wih2,
                        const float* __restrict__ Whh2,
                        const float* __restrict__ bih2,
                        const float* __restrict__ bhh2,
                        const float* __restrict__ Wlin,
                        const float* __restrict__ blin,
                        float* __restrict__ out)
{
    __shared__ Smem s;
    const int j   = threadIdx.x;
    const int bb0 = blockIdx.x * NB;

    const int  hh   = (j >= 224);           // k-half (uniform per warp)
    const int  r    = hh ? (j - 224) : j;   // gate row
    const bool work = (r < G4) && (hh ? (j >= 224) : (j < G4));
    const bool isOut = (j >= 204 && j < 208);
    const bool isX   = (j >= 208 && j < 212);
    const int  ko   = 28 * hh;              // k-float base of this half

    // ---------------- prologue: half-row weights to registers ----------------
    u64 w1p[14], wap[14], wbp[14];
    float bj1 = 0.f, bj2 = 0.f, wi1 = 0.f;
    if (work) {
        load_half(Whh1 + r * H, ko, w1p);
        load_half(Wih2 + r * H, ko, wap);
        load_half(Whh2 + r * H, ko, wbp);
        if (hh == 0) {                       // bias & input term only in half0
            bj1 = bih1[r] + bhh1[r];
            wi1 = Wih1[r];
            bj2 = bih2[r] + bhh2[r];
        }
    }

    // update ownership: half0 worker owns c1(b1,u1); half1 worker owns c2
    const int b1 = work ? (r / H) : 0;
    const int u1 = work ? (r % H) : 0;
    float c1 = 0.f, c2 = 0.f;

    // init shared state
    for (int idx = j; idx < NB * WPAD; idx += NTH) {
        (&s.h1[0][0])[idx] = 0.f;
        (&s.h2[0][0])[idx] = 0.f;
    }
    if (j < WPAD) s.WL[j] = (j < H) ? Wlin[j] : 0.f;
    if (j < NB) {
        s.X[j]    = input[(size_t)(bb0 + j) * T];
        s.OUTB[j] = 0.f;
    }
    if (j == 0) s.blin = blin[0];

    // ------------------------------ main loop (t = 0..T-1) ------------------------------
    for (int t = 0; t < T; t++) {
        __syncthreads();                                        // S1: h/X/G stable
        float xr = 0.f;

        // phase A: gate1 partials + out-dot(t-1) + x prefetch
        if (work) {
            u64 acc[NB];
            #pragma unroll
            for (int b = 0; b < NB; b++)
                acc[b] = (hh == 0) ? pack2(fmaf(wi1, s.X[b], bj1), 0.f)
                                   : pack2(0.f, 0.f);
            #pragma unroll
            for (int c = 0; c < 7; c++) {
                #pragma unroll
                for (int b = 0; b < NB; b++) {
                    ulonglong2 hv = *(const ulonglong2*)&s.h1[b][ko + 4 * c];
                    acc[b] = ffma2(w1p[2 * c],     hv.x, acc[b]);
                    acc[b] = ffma2(w1p[2 * c + 1], hv.y, acc[b]);
                }
            }
            #pragma unroll
            for (int b = 0; b < NB; b++) s.G1[b][2 * r + hh] = hsum2(acc[b]);
        }
        if (isOut && t >= 1) {                     // output for step t-1
            const int b = j - 204;
            float a0 = 0.f, a1 = 0.f, a2 = 0.f, a3 = 0.f;
            #pragma unroll
            for (int p = 0; p < 14; p++) {
                float4 w = *(const float4*)&s.WL[4 * p];
                float4 h = *(const float4*)&s.h2[b][4 * p];
                a0 = fmaf(w.x, h.x, a0);  a1 = fmaf(w.y, h.y, a1);
                a2 = fmaf(w.z, h.z, a2);  a3 = fmaf(w.w, h.w, a3);
            }
            out[(size_t)(bb0 + b) * TT + (t - 1)] = (a0 + a1) + (a2 + a3) + s.blin;
        }
        if (isX) {
            int b = j - 208;
            xr = (t + 1 < T) ? input[(size_t)(bb0 + b) * T + (t + 1)] : 0.f;
        }
        __syncthreads();                                        // S2: G1 visible

        // phase B: update1 (half0 workers)
        if (work && hh == 0) {
            float2 vi = *(const float2*)&s.G1[b1][2 * u1];
            float2 vf = *(const float2*)&s.G1[b1][2 * (H + u1)];
            float2 vg = *(const float2*)&s.G1[b1][2 * (2 * H + u1)];
            float2 vo = *(const float2*)&s.G1[b1][2 * (3 * H + u1)];
            s.h1[b1][u1] = lstm_act(vi.x + vi.y, vf.x + vf.y,
                                    vg.x + vg.y, vo.x + vo.y, c1);
        }
        __syncthreads();                                        // S3: h1 visible

        // phase C: gate2 partials
        if (work) {
            u64 acc[NB];
            #pragma unroll
            for (int b = 0; b < NB; b++)
                acc[b] = (hh == 0) ? pack2(bj2, 0.f) : pack2(0.f, 0.f);
            #pragma unroll
            for (int c = 0; c < 7; c++) {
                #pragma unroll
                for (int b = 0; b < NB; b++) {
                    ulonglong2 h1v = *(const ulonglong2*)&s.h1[b][ko + 4 * c];
                    ulonglong2 h2v = *(const ulonglong2*)&s.h2[b][ko + 4 * c];
                    acc[b] = ffma2(wap[2 * c],     h1v.x, acc[b]);
                    acc[b] = ffma2(wap[2 * c + 1], h1v.y, acc[b]);
                    acc[b] = ffma2(wbp[2 * c],     h2v.x, acc[b]);
                    acc[b] = ffma2(wbp[2 * c + 1], h2v.y, acc[b]);
                }
            }
            #pragma unroll
            for (int b = 0; b < NB; b++) s.G2[b][2 * r + hh] = hsum2(acc[b]);
        }
        __syncthreads();                                        // S4: G2 visible

        // phase D: update2 (half1 workers) + publish x
        if (work && hh == 1) {
            float2 vi = *(const float2*)&s.G2[b1][2 * u1];
            float2 vf = *(const float2*)&s.G2[b1][2 * (H + u1)];
            float2 vg = *(const float2*)&s.G2[b1][2 * (2 * H + u1)];
            float2 vo = *(const float2*)&s.G2[b1][2 * (3 * H + u1)];
            s.h2[b1][u1] = lstm_act(vi.x + vi.y, vf.x + vf.y,
                                    vg.x + vg.y, vo.x + vo.y, c2);
        }
        if (isX) s.X[j - 208] = xr;
    }

    // ---------------------- autoregressive tail (t = T..TT-1) ----------------------
    for (int t = T; t < TT; t++) {
        __syncthreads();
        // phase O: output for step t-1 -> OUTB (feeds gate1 below)
        if (isOut) {
            const int b = j - 204;
            float a0 = 0.f, a1 = 0.f, a2 = 0.f, a3 = 0.f;
            #pragma unroll
            for (int p = 0; p < 14; p++) {
                float4 w = *(const float4*)&s.WL[4 * p];
                float4 h = *(const float4*)&s.h2[b][4 * p];
                a0 = fmaf(w.x, h.x, a0);  a1 = fmaf(w.y, h.y, a1);
                a2 = fmaf(w.z, h.z, a2);  a3 = fmaf(w.w, h.w, a3);
            }
            float val = (a0 + a1) + (a2 + a3) + s.blin;
            out[(size_t)(bb0 + b) * TT + (t - 1)] = val;
            s.OUTB[b] = val;
        }
        __syncthreads();
        // gate1 with x = OUTB
        if (work) {
            u64 acc[NB];
            #pragma unroll
            for (int b = 0; b < NB; b++)
                acc[b] = (hh == 0) ? pack2(fmaf(wi1, s.OUTB[b], bj1), 0.f)
                                   : pack2(0.f, 0.f);
            #pragma unroll
            for (int c = 0; c < 7; c++) {
                #pragma unroll
                for (int b = 0; b < NB; b++) {
                    ulonglong2 hv = *(const ulonglong2*)&s.h1[b][ko + 4 * c];
                    acc[b] = ffma2(w1p[2 * c],     hv.x, acc[b]);
                    acc[b] = ffma2(w1p[2 * c + 1], hv.y, acc[b]);
                }
            }
            #pragma unroll
            for (int b = 0; b < NB; b++) s.G1[b][2 * r + hh] = hsum2(acc[b]);
        }
        __syncthreads();
        if (work && hh == 0) {
            float2 vi = *(const float2*)&s.G1[b1][2 * u1];
            float2 vf = *(const float2*)&s.G1[b1][2 * (H + u1)];
            float2 vg = *(const float2*)&s.G1[b1][2 * (2 * H + u1)];
            float2 vo = *(const float2*)&s.G1[b1][2 * (3 * H + u1)];
            s.h1[b1][u1] = lstm_act(vi.x + vi.y, vf.x + vf.y,
                                    vg.x + vg.y, vo.x + vo.y, c1);
        }
        __syncthreads();
        if (work) {
            u64 acc[NB];
            #pragma unroll
            for (int b = 0; b < NB; b++)
                acc[b] = (hh == 0) ? pack2(bj2, 0.f) : pack2(0.f, 0.f);
            #pragma unroll
            for (int c = 0; c < 7; c++) {
                #pragma unroll
                for (int b = 0; b < NB; b++) {
                    ulonglong2 h1v = *(const ulonglong2*)&s.h1[b][ko + 4 * c];
                    ulonglong2 h2v = *(const ulonglong2*)&s.h2[b][ko + 4 * c];
                    acc[b] = ffma2(wap[2 * c],     h1v.x, acc[b]);
                    acc[b] = ffma2(wap[2 * c + 1], h1v.y, acc[b]);
                    acc[b] = ffma2(wbp[2 * c],     h2v.x, acc[b]);
                    acc[b] = ffma2(wbp[2 * c + 1], h2v.y, acc[b]);
                }
            }
            #pragma unroll
            for (int b = 0; b < NB; b++) s.G2[b][2 * r + hh] = hsum2(acc[b]);
        }
        __syncthreads();
        if (work && hh == 1) {
            float2 vi = *(const float2*)&s.G2[b1][2 * u1];
            float2 vf = *(const float2*)&s.G2[b1][2 * (H + u1)];
            float2 vg = *(const float2*)&s.G2[b1][2 * (2 * H + u1)];
            float2 vo = *(const float2*)&s.G2[b1][2 * (3 * H + u1)];
            s.h2[b1][u1] = lstm_act(vi.x + vi.y, vf.x + vf.y,
                                    vg.x + vg.y, vo.x + vo.y, c2);
        }
    }

    // final output (step TT-1)
    __syncthreads();
    if (isOut) {
        const int b = j - 204;
        float a0 = 0.f, a1 = 0.f, a2 = 0.f, a3 = 0.f;
        #pragma unroll
        for (int p = 0; p < 14; p++) {
            float4 w = *(const float4*)&s.WL[4 * p];
            float4 h = *(const float4*)&s.h2[b][4 * p];
            a0 = fmaf(w.x, h.x, a0);  a1 = fmaf(w.y, h.y, a1);
            a2 = fmaf(w.z, h.z, a2);  a3 = fmaf(w.w, h.w, a3);
        }
        out[(size_t)(bb0 + b) * TT + (TT - 1)] = (a0 + a1) + (a2 + a3) + s.blin;
    }
}

extern "C" void kernel_launch(void* const* d_in, const int* in_sizes, int n_in,
                              void* d_out, int out_size)
{
    const float* input = (const float*)d_in[0];
    const float* Wih1  = (const float*)d_in[1];
    const float* Whh1  = (const float*)d_in[2];
    const float* bih1  = (const float*)d_in[3];
    const float* bhh1  = (const float*)d_in[4];
    const float* Wih2  = (const float*)d_in[5];
    const float* Whh2  = (const float*)d_in[6];
    const float* bih2  = (const float*)d_in[7];
    const float* bhh2  = (const float*)d_in[8];
    const float* Wlin  = (const float*)d_in[9];
    const float* blin  = (const float*)d_in[10];
    float* out = (float*)d_out;

    lstm_ksplit_kernel<<<NBLK, NTH>>>(
        input, Wih1, Whh1, bih1, bhh1, Wih2, Whh2, bih2, bhh2, Wlin, blin, out);
}